// round 9
// baseline (speedup 1.0000x reference)
#include <cuda_runtime.h>
#include <cuda_fp16.h>
#include <cstdint>

#define NB 16
#define HH 224
#define WW 224
#define GX 7
#define GY 28
#define NBLK (GX*GY*NB)      // 3136
#define NELEM 25690112       // 16*32*224*224

// 2-way fp16 split planes, NHWC (c contiguous): x = s1 + s2 + O(2^-22 x)
__device__ __align__(16) __half g_s1[NELEM];
__device__ __align__(16) __half g_s2[NELEM];
__device__ double g_part[NBLK * 64];
__device__ float  g_scale[32];
__device__ float  g_bias[32];

__device__ __forceinline__ uint32_t smem_u32(const void* p) {
    uint32_t a;
    asm("{ .reg .u64 t; cvta.to.shared.u64 t, %1; cvt.u32.u64 %0, t; }" : "=r"(a) : "l"(p));
    return a;
}
__device__ __forceinline__ void ldsm4(uint32_t* r, uint32_t addr) {
    asm volatile("ldmatrix.sync.aligned.m8n8.x4.shared.b16 {%0,%1,%2,%3}, [%4];"
        : "=r"(r[0]), "=r"(r[1]), "=r"(r[2]), "=r"(r[3]) : "r"(addr));
}
__device__ __forceinline__ void ldsm4t(uint32_t* r, uint32_t addr) {
    asm volatile("ldmatrix.sync.aligned.m8n8.x4.trans.shared.b16 {%0,%1,%2,%3}, [%4];"
        : "=r"(r[0]), "=r"(r[1]), "=r"(r[2]), "=r"(r[3]) : "r"(addr));
}
__device__ __forceinline__ void mma4(float* d, const uint32_t* a, uint32_t b0, uint32_t b1) {
    asm volatile("mma.sync.aligned.m16n8k16.row.col.f32.f16.f16.f32 "
        "{%0,%1,%2,%3}, {%4,%5,%6,%7}, {%8,%9}, {%0,%1,%2,%3};"
        : "+f"(d[0]), "+f"(d[1]), "+f"(d[2]), "+f"(d[3])
        : "r"(a[0]), "r"(a[1]), "r"(a[2]), "r"(a[3]), "r"(b0), "r"(b1));
}

// ---------------------------------------------------------------------------
// Pre-pass: NCHW fp32 -> 2 NHWC fp16 split planes
// ---------------------------------------------------------------------------
__global__ __launch_bounds__(256)
void split_kernel(const float* __restrict__ x)
{
    __shared__ float sm[32 * 33];
    const int t = threadIdx.x, w0 = blockIdx.x * 32, h = blockIdx.y, n = blockIdx.z;
    {
        int c = t >> 3, j = t & 7;
        float4 v = *(const float4*)(x + (((size_t)(n * 32 + c) * 224 + h) * 224 + w0 + j * 4));
        sm[(j*4+0)*33+c] = v.x; sm[(j*4+1)*33+c] = v.y;
        sm[(j*4+2)*33+c] = v.z; sm[(j*4+3)*33+c] = v.w;
    }
    __syncthreads();
    const int ww = t >> 3, jj = t & 7;
    const size_t ob = ((size_t)((n * 224 + h) * 224) + (w0 + ww)) * 32 + jj * 4;
    unsigned short p1[4], p2[4];
#pragma unroll
    for (int i = 0; i < 4; i++) {
        float v0 = sm[ww * 33 + jj * 4 + i];
        __half h1 = __float2half_rn(v0);
        float r1 = v0 - __half2float(h1);
        p1[i] = __half_as_ushort(h1);
        p2[i] = __half_as_ushort(__float2half_rn(r1));
    }
    *(uint2*)((unsigned short*)g_s1 + ob) =
        make_uint2((unsigned)p1[0] | ((unsigned)p1[1] << 16), (unsigned)p1[2] | ((unsigned)p1[3] << 16));
    *(uint2*)((unsigned short*)g_s2 + ob) =
        make_uint2((unsigned)p2[0] | ((unsigned)p2[1] << 16), (unsigned)p2[2] | ((unsigned)p2[3] << 16));
}

// ---------------------------------------------------------------------------
// Conv: HMMA (mma.sync m16n8k16 f16->f32) implicit GEMM.
// CTA = (n, 8h x 32w): M=256 positions, N=32 co. Warp hh = one h row (32 w).
// A: both split planes staged once, 340 halo pos x 32 fp16, pitch 80B
// (conflict-free ldmatrix, gcd(5,8)=1). B: 288 k x 32 o fp16, pitch 80B.
// Mainloop: 9 taps x 2 k16-chunks x { B 2 ldsm4t ; per split: A 2 ldsm4, 8 mma }.
// ---------------------------------------------------------------------------
#define A_PLANE_B 27200     // 340 * 80
#define B_OFF     54400     // 2 planes
#define CONV_SMEM 77440     // + 288*80 B

__global__ __launch_bounds__(256, 2)
void conv_kernel(const float* __restrict__ wgt, float* __restrict__ out)
{
    extern __shared__ unsigned char dsm[];
    __half* Bsm = (__half*)(dsm + B_OFF);
    float* smt = (float*)dsm;            // alias after mainloop: 256 m x 36 f32
    __shared__ double sred[512];

    const int tid = threadIdx.x;
    const int l = tid & 31, hh = tid >> 5;
    const int w0 = blockIdx.x * 32, h0 = blockIdx.y * 8, n = blockIdx.z;
    const uint32_t Abase = smem_u32(dsm);
    const uint32_t Bbase = smem_u32(Bsm);
    const uint32_t laneoff = (uint32_t)(((((l >> 3) & 1) * 8) + (l & 7)) * 80 + (l >> 4) * 16);

    // ---- stage B: binarized weights fp16, Bsm[k = tap*32+c][o], pitch 40 h ----
    for (int i = tid; i < 288 * 32; i += 256) {
        int k = i >> 5, o = i & 31;
        int tap = k >> 5, c = k & 31;
        Bsm[k * 40 + o] = __float2half_rn((wgt[o * 288 + c * 9 + tap] >= 0.0f) ? 1.0f : -1.0f);
    }
    // ---- stage A: both planes, 340 halo positions x 64B payload (4 x 16B) ----
    for (int i = tid; i < 2720; i += 256) {
        int plane = i / 1360, rem = i - plane * 1360;
        int pos = rem >> 2, q = rem & 3;
        int hr = pos / 34, hc = pos - hr * 34;
        int gh = h0 + hr - 1, gw = w0 + hc - 1;
        uint4 v = make_uint4(0u, 0u, 0u, 0u);
        if (gh >= 0 && gh < HH && gw >= 0 && gw < WW) {
            const __half* pl = plane ? g_s2 : g_s1;
            v = *(const uint4*)(pl + (size_t)((n * 224 + gh) * 224 + gw) * 32 + q * 8);
        }
        *(uint4*)(dsm + plane * A_PLANE_B + pos * 80 + q * 16) = v;
    }
    __syncthreads();

    float acc[2][4][4];
#pragma unroll
    for (int a = 0; a < 2; a++)
#pragma unroll
        for (int b = 0; b < 4; b++)
#pragma unroll
            for (int c = 0; c < 4; c++) acc[a][b][c] = 0.0f;

#pragma unroll
    for (int tap = 0; tap < 9; tap++) {
        const int dy = tap / 3, dx = tap - (tap / 3) * 3;
#pragma unroll
        for (int ch = 0; ch < 2; ch++) {
            uint32_t Bf[8];
            uint32_t bp = Bbase + (uint32_t)((tap * 32 + ch * 16) * 80) + laneoff;
            ldsm4t(Bf,     bp);          // o 0-15 : {b0,b1 | b0,b1}
            ldsm4t(Bf + 4, bp + 32);     // o 16-31
            const uint32_t apos = (uint32_t)((((hh + dy) * 34 + dx) * 80) + ch * 32) + laneoff;
#pragma unroll
            for (int s = 0; s < 2; s++) {
                uint32_t A0[4], A1[4];
                uint32_t ap = Abase + (uint32_t)(s * A_PLANE_B) + apos;
                ldsm4(A0, ap);
                ldsm4(A1, ap + 1280);    // +16 positions (mi=1)
#pragma unroll
                for (int ni = 0; ni < 4; ni++) {
                    mma4(acc[0][ni], A0, Bf[ni * 2], Bf[ni * 2 + 1]);
                    mma4(acc[1][ni], A1, Bf[ni * 2], Bf[ni * 2 + 1]);
                }
            }
        }
    }

    // ---- epilogue: accums -> smt[m][o] (pitch 36), stats, coalesced store ----
    __syncthreads();   // done reading A/B smem; smt aliases them
    {
        const int g = l >> 2, t4 = l & 3;
#pragma unroll
        for (int mi = 0; mi < 2; mi++) {
            int m0 = hh * 32 + mi * 16 + g;
#pragma unroll
            for (int ni = 0; ni < 4; ni++) {
                int o0 = ni * 8 + 2 * t4;
                smt[m0 * 36 + o0]           = acc[mi][ni][0];
                smt[m0 * 36 + o0 + 1]       = acc[mi][ni][1];
                smt[(m0 + 8) * 36 + o0]     = acc[mi][ni][2];
                smt[(m0 + 8) * 36 + o0 + 1] = acc[mi][ni][3];
            }
        }
    }
    __syncthreads();

    // BN stats: f32 inner (32 values), double outer (fixed order -> deterministic)
    {
        const int o = tid & 31, part = tid >> 5;
        float s = 0.0f, q = 0.0f;
#pragma unroll
        for (int m = part * 32; m < part * 32 + 32; m++) {
            float v = smt[m * 36 + o];
            s += v;
            q = fmaf(v, v, q);
        }
        sred[o * 8 + part]       = (double)s;
        sred[256 + o * 8 + part] = (double)q;
    }

    // Store: thread = position m; per o, warp lanes = 32 consecutive w (coalesced)
    {
        const int hhm = tid >> 5, wwm = tid & 31;
        float* obase = out + ((size_t)n * 32 * 224 + (size_t)(h0 + hhm)) * 224 + w0 + wwm;
#pragma unroll
        for (int j = 0; j < 8; j++) {
            float v0 = smt[tid * 36 + j * 4 + 0];
            float v1 = smt[tid * 36 + j * 4 + 1];
            float v2 = smt[tid * 36 + j * 4 + 2];
            float v3 = smt[tid * 36 + j * 4 + 3];
            obase[(size_t)(j * 4 + 0) * 224 * 224] = v0;
            obase[(size_t)(j * 4 + 1) * 224 * 224] = v1;
            obase[(size_t)(j * 4 + 2) * 224 * 224] = v2;
            obase[(size_t)(j * 4 + 3) * 224 * 224] = v3;
        }
    }
    __syncthreads();

    const int bflat = blockIdx.x + GX * (blockIdx.y + GY * blockIdx.z);
    if (tid < 64) {
        int cch = tid & 31, which = tid >> 5;
        double a = 0.0;
#pragma unroll
        for (int j = 0; j < 8; j++)
            a += sred[which * 256 + cch * 8 + j];
        g_part[bflat * 64 + which * 32 + cch] = a;
    }
}

// ---------------------------------------------------------------------------
__global__ void reduce_kernel(const float* __restrict__ gamma,
                              const float* __restrict__ beta)
{
    const int c = blockIdx.x, t = threadIdx.x;   // 32 blocks x 256 threads
    __shared__ double sh[512];
    double s = 0.0, q = 0.0;
    for (int b = t; b < NBLK; b += 256) {
        s += g_part[b * 64 + c];
        q += g_part[b * 64 + 32 + c];
    }
    sh[t] = s; sh[256 + t] = q;
    __syncthreads();
    for (int step = 128; step > 0; step >>= 1) {
        if (t < step) { sh[t] += sh[t + step]; sh[256 + t] += sh[256 + t + step]; }
        __syncthreads();
    }
    if (t == 0) {
        const double Nc = (double)NB * HH * WW;
        double mean = sh[0] / Nc;
        double var  = sh[256] / Nc - mean * mean;
        double inv  = 1.0 / sqrt(var + 1e-5);
        double sc   = (double)gamma[c] * inv;
        g_scale[c] = (float)sc;
        g_bias[c]  = (float)((double)beta[c] - mean * sc);
    }
}

// ---------------------------------------------------------------------------
__device__ __forceinline__ float qclamp(float v, float sc, float bi)
{
    float y = fmaf(v, sc, bi);
    y = fminf(fmaxf(y, -1.0f), 1.0f);
    return rintf(y * 2.0f) * 0.5f;
}

__global__ void finalize_kernel(float4* __restrict__ out)
{
    const unsigned i = blockIdx.x * 256u + threadIdx.x;   // < 6422528
    const int c = (int)((i / 12544u) & 31u);
    const float sc = g_scale[c], bi = g_bias[c];
    float4 v = out[i];
    v.x = qclamp(v.x, sc, bi); v.y = qclamp(v.y, sc, bi);
    v.z = qclamp(v.z, sc, bi); v.w = qclamp(v.w, sc, bi);
    out[i] = v;
}

// ---------------------------------------------------------------------------
extern "C" void kernel_launch(void* const* d_in, const int* in_sizes, int n_in,
                              void* d_out, int out_size)
{
    const float* x     = (const float*)d_in[0];
    const float* wgt   = (const float*)d_in[1];
    const float* gamma = (const float*)d_in[2];
    const float* beta  = (const float*)d_in[3];
    float* out = (float*)d_out;

    cudaFuncSetAttribute(conv_kernel, cudaFuncAttributeMaxDynamicSharedMemorySize, CONV_SMEM);

    split_kernel<<<dim3(7, 224, NB), 256>>>(x);
    conv_kernel<<<dim3(GX, GY, NB), 256, CONV_SMEM>>>(wgt, out);
    reduce_kernel<<<32, 256>>>(gamma, beta);
    finalize_kernel<<<25088, 256>>>((float4*)d_out);
}

// round 14
// speedup vs baseline: 1.4103x; 1.4103x over previous
#include <cuda_runtime.h>
#include <cuda_fp16.h>
#include <cstdint>

#define NB 16
#define HH 224
#define WW 224
#define GX 7
#define GY 28
#define NBLK (GX*GY*NB)      // 3136
#define NPIX 50176           // 224*224

__device__ double g_part[NBLK * 64];
__device__ float  g_scale[32];
__device__ float  g_bias[32];

__device__ __forceinline__ uint32_t smem_u32(const void* p) {
    uint32_t a;
    asm("{ .reg .u64 t; cvta.to.shared.u64 t, %1; cvt.u32.u64 %0, t; }" : "=r"(a) : "l"(p));
    return a;
}
__device__ __forceinline__ void ldsm4(uint32_t* r, uint32_t addr) {
    asm volatile("ldmatrix.sync.aligned.m8n8.x4.shared.b16 {%0,%1,%2,%3}, [%4];"
        : "=r"(r[0]), "=r"(r[1]), "=r"(r[2]), "=r"(r[3]) : "r"(addr));
}
__device__ __forceinline__ void ldsm4t(uint32_t* r, uint32_t addr) {
    asm volatile("ldmatrix.sync.aligned.m8n8.x4.trans.shared.b16 {%0,%1,%2,%3}, [%4];"
        : "=r"(r[0]), "=r"(r[1]), "=r"(r[2]), "=r"(r[3]) : "r"(addr));
}
__device__ __forceinline__ void mma4(float* d, const uint32_t* a, uint32_t b0, uint32_t b1) {
    asm volatile("mma.sync.aligned.m16n8k16.row.col.f32.f16.f16.f32 "
        "{%0,%1,%2,%3}, {%4,%5,%6,%7}, {%8,%9}, {%0,%1,%2,%3};"
        : "+f"(d[0]), "+f"(d[1]), "+f"(d[2]), "+f"(d[3])
        : "r"(a[0]), "r"(a[1]), "r"(a[2]), "r"(a[3]), "r"(b0), "r"(b1));
}

// ---------------------------------------------------------------------------
// Fused conv: in-kernel 2-way fp16 split + HMMA implicit GEMM.
// CTA = (n, 8h x 32w): M=256 positions, N=32 co. Warp hh = one h row (32 w).
// Staging: read fp32 x tile (NCHW, 10x34 halo x 32c), split each value into
// h1 + h2 (x = h1 + h2 + O(2^-22 x)), store both fp16 planes to smem
// [pos][c] with 80B pitch (conflict-free ldmatrix, gcd(5,8)=1).
// B: binarized weights fp16, 288 k x 32 o, pitch 80B.
// Mainloop: 9 taps x 2 k16-chunks x { 2 ldsm4t(B); per plane: 2 ldsm4(A), 8 mma }.
// ---------------------------------------------------------------------------
#define A_PLANE_B 27200     // 340 * 80
#define B_OFF     54400     // 2 planes
#define CONV_SMEM 77440     // + 288*80 B

__global__ __launch_bounds__(256, 2)
void conv_kernel(const float* __restrict__ x, const float* __restrict__ wgt,
                 float* __restrict__ out)
{
    extern __shared__ unsigned char dsm[];
    __half* Bsm = (__half*)(dsm + B_OFF);
    float* smt = (float*)dsm;            // alias after mainloop: 256 m x 36 f32
    __shared__ double sred[512];

    const int tid = threadIdx.x;
    const int l = tid & 31, hh = tid >> 5;
    const int w0 = blockIdx.x * 32, h0 = blockIdx.y * 8, n = blockIdx.z;
    const uint32_t Abase = smem_u32(dsm);
    const uint32_t Bbase = smem_u32(Bsm);
    const uint32_t laneoff = (uint32_t)(((((l >> 3) & 1) * 8) + (l & 7)) * 80 + (l >> 4) * 16);

    // ---- stage B: binarized weights fp16, Bsm[k = tap*32+c][o], pitch 40 h ----
    for (int i = tid; i < 288 * 32; i += 256) {
        int k = i >> 5, o = i & 31;
        int tap = k >> 5, c = k & 31;
        Bsm[k * 40 + o] = __float2half_rn((wgt[o * 288 + c * 9 + tap] >= 0.0f) ? 1.0f : -1.0f);
    }
    // ---- stage A: fp32 x tile -> 2 fp16 split planes in smem ----
    // 10880 = 32 c * 340 halo positions; consecutive i -> consecutive w (coalesced runs)
    for (int i = tid; i < 10880; i += 256) {
        const int c = i / 340, rem = i - c * 340;
        const int hr = rem / 34, hc = rem - hr * 34;
        const int gh = h0 + hr - 1, gw = w0 + hc - 1;
        float v = 0.0f;
        if (gh >= 0 && gh < HH && gw >= 0 && gw < WW)
            v = x[((size_t)(n * 32 + c) * HH + gh) * WW + gw];
        const __half h1 = __float2half_rn(v);
        const __half h2 = __float2half_rn(v - __half2float(h1));
        const int po = rem * 80 + c * 2;
        *(__half*)(dsm + po)             = h1;
        *(__half*)(dsm + A_PLANE_B + po) = h2;
    }
    __syncthreads();

    float acc[2][4][4];
#pragma unroll
    for (int a = 0; a < 2; a++)
#pragma unroll
        for (int b = 0; b < 4; b++)
#pragma unroll
            for (int c = 0; c < 4; c++) acc[a][b][c] = 0.0f;

#pragma unroll
    for (int tap = 0; tap < 9; tap++) {
        const int dy = tap / 3, dx = tap - (tap / 3) * 3;
#pragma unroll
        for (int ch = 0; ch < 2; ch++) {
            uint32_t Bf[8];
            uint32_t bp = Bbase + (uint32_t)((tap * 32 + ch * 16) * 80) + laneoff;
            ldsm4t(Bf,     bp);          // o 0-15 : {b0,b1 | b0,b1}
            ldsm4t(Bf + 4, bp + 32);     // o 16-31
            const uint32_t apos = (uint32_t)((((hh + dy) * 34 + dx) * 80) + ch * 32) + laneoff;
#pragma unroll
            for (int s = 0; s < 2; s++) {
                uint32_t A0[4], A1[4];
                uint32_t ap = Abase + (uint32_t)(s * A_PLANE_B) + apos;
                ldsm4(A0, ap);
                ldsm4(A1, ap + 1280);    // +16 positions (mi=1)
#pragma unroll
                for (int ni = 0; ni < 4; ni++) {
                    mma4(acc[0][ni], A0, Bf[ni * 2], Bf[ni * 2 + 1]);
                    mma4(acc[1][ni], A1, Bf[ni * 2], Bf[ni * 2 + 1]);
                }
            }
        }
    }

    // ---- epilogue: accums -> smt[m][o] (pitch 36), stats, coalesced store ----
    __syncthreads();   // done reading A/B smem; smt aliases them
    {
        const int g = l >> 2, t4 = l & 3;
#pragma unroll
        for (int mi = 0; mi < 2; mi++) {
            int m0 = hh * 32 + mi * 16 + g;
#pragma unroll
            for (int ni = 0; ni < 4; ni++) {
                int o0 = ni * 8 + 2 * t4;
                smt[m0 * 36 + o0]           = acc[mi][ni][0];
                smt[m0 * 36 + o0 + 1]       = acc[mi][ni][1];
                smt[(m0 + 8) * 36 + o0]     = acc[mi][ni][2];
                smt[(m0 + 8) * 36 + o0 + 1] = acc[mi][ni][3];
            }
        }
    }
    __syncthreads();

    // BN stats: f32 inner (32 values), double outer (fixed order -> deterministic)
    {
        const int o = tid & 31, part = tid >> 5;
        float s = 0.0f, q = 0.0f;
#pragma unroll
        for (int m = part * 32; m < part * 32 + 32; m++) {
            float v = smt[m * 36 + o];
            s += v;
            q = fmaf(v, v, q);
        }
        sred[o * 8 + part]       = (double)s;
        sred[256 + o * 8 + part] = (double)q;
    }

    // Store: thread = position m; per o, warp lanes = 32 consecutive w (coalesced)
    {
        const int hhm = tid >> 5, wwm = tid & 31;
        float* obase = out + (size_t)n * 32 * NPIX
                           + (size_t)(h0 + hhm) * 224 + w0 + wwm;
#pragma unroll
        for (int j = 0; j < 8; j++) {
            float v0 = smt[tid * 36 + j * 4 + 0];
            float v1 = smt[tid * 36 + j * 4 + 1];
            float v2 = smt[tid * 36 + j * 4 + 2];
            float v3 = smt[tid * 36 + j * 4 + 3];
            obase[(size_t)(j * 4 + 0) * NPIX] = v0;
            obase[(size_t)(j * 4 + 1) * NPIX] = v1;
            obase[(size_t)(j * 4 + 2) * NPIX] = v2;
            obase[(size_t)(j * 4 + 3) * NPIX] = v3;
        }
    }
    __syncthreads();

    const int bflat = blockIdx.x + GX * (blockIdx.y + GY * blockIdx.z);
    if (tid < 64) {
        int cch = tid & 31, which = tid >> 5;
        double a = 0.0;
#pragma unroll
        for (int j = 0; j < 8; j++)
            a += sred[which * 256 + cch * 8 + j];
        g_part[bflat * 64 + which * 32 + cch] = a;
    }
}

// ---------------------------------------------------------------------------
__global__ void reduce_kernel(const float* __restrict__ gamma,
                              const float* __restrict__ beta)
{
    const int c = blockIdx.x, t = threadIdx.x;   // 32 blocks x 256 threads
    __shared__ double sh[512];
    double s = 0.0, q = 0.0;
    for (int b = t; b < NBLK; b += 256) {
        s += g_part[b * 64 + c];
        q += g_part[b * 64 + 32 + c];
    }
    sh[t] = s; sh[256 + t] = q;
    __syncthreads();
    for (int step = 128; step > 0; step >>= 1) {
        if (t < step) { sh[t] += sh[t + step]; sh[256 + t] += sh[256 + t + step]; }
        __syncthreads();
    }
    if (t == 0) {
        const double Nc = (double)NB * HH * WW;
        double mean = sh[0] / Nc;
        double var  = sh[256] / Nc - mean * mean;
        double inv  = 1.0 / sqrt(var + 1e-5);
        double sc   = (double)gamma[c] * inv;
        g_scale[c] = (float)sc;
        g_bias[c]  = (float)((double)beta[c] - mean * sc);
    }
}

// ---------------------------------------------------------------------------
__device__ __forceinline__ float qclamp(float v, float sc, float bi)
{
    float y = fmaf(v, sc, bi);
    y = fminf(fmaxf(y, -1.0f), 1.0f);
    return rintf(y * 2.0f) * 0.5f;
}

__global__ void finalize_kernel(float4* __restrict__ out)
{
    const unsigned i = blockIdx.x * 256u + threadIdx.x;   // < 6422528
    const int c = (int)((i / 12544u) & 31u);
    const float sc = g_scale[c], bi = g_bias[c];
    float4 v = out[i];
    v.x = qclamp(v.x, sc, bi); v.y = qclamp(v.y, sc, bi);
    v.z = qclamp(v.z, sc, bi); v.w = qclamp(v.w, sc, bi);
    out[i] = v;
}

// ---------------------------------------------------------------------------
extern "C" void kernel_launch(void* const* d_in, const int* in_sizes, int n_in,
                              void* d_out, int out_size)
{
    const float* x     = (const float*)d_in[0];
    const float* wgt   = (const float*)d_in[1];
    const float* gamma = (const float*)d_in[2];
    const float* beta  = (const float*)d_in[3];
    float* out = (float*)d_out;

    cudaFuncSetAttribute(conv_kernel, cudaFuncAttributeMaxDynamicSharedMemorySize, CONV_SMEM);

    conv_kernel<<<dim3(GX, GY, NB), 256, CONV_SMEM>>>(x, wgt, out);
    reduce_kernel<<<32, 256>>>(gamma, beta);
    finalize_kernel<<<25088, 256>>>((float4*)d_out);
}

// round 16
// speedup vs baseline: 1.7621x; 1.2494x over previous
#include <cuda_runtime.h>
#include <cuda_fp16.h>
#include <cstdint>

#define NB 16
#define HH 224
#define WW 224
#define GX 7
#define GY 28
#define NBLK (GX*GY*NB)      // 3136
#define NPIX 50176           // 224*224

__device__ double g_part[NBLK * 64];
__device__ float  g_scale[32];
__device__ float  g_bias[32];

__device__ __forceinline__ uint32_t smem_u32(const void* p) {
    uint32_t a;
    asm("{ .reg .u64 t; cvta.to.shared.u64 t, %1; cvt.u32.u64 %0, t; }" : "=r"(a) : "l"(p));
    return a;
}
__device__ __forceinline__ void ldsm4(uint32_t* r, uint32_t addr) {
    asm volatile("ldmatrix.sync.aligned.m8n8.x4.shared.b16 {%0,%1,%2,%3}, [%4];"
        : "=r"(r[0]), "=r"(r[1]), "=r"(r[2]), "=r"(r[3]) : "r"(addr));
}
__device__ __forceinline__ void ldsm4t(uint32_t* r, uint32_t addr) {
    asm volatile("ldmatrix.sync.aligned.m8n8.x4.trans.shared.b16 {%0,%1,%2,%3}, [%4];"
        : "=r"(r[0]), "=r"(r[1]), "=r"(r[2]), "=r"(r[3]) : "r"(addr));
}
__device__ __forceinline__ void mma4(float* d, const uint32_t* a, uint32_t b0, uint32_t b1) {
    asm volatile("mma.sync.aligned.m16n8k16.row.col.f32.f16.f16.f32 "
        "{%0,%1,%2,%3}, {%4,%5,%6,%7}, {%8,%9}, {%0,%1,%2,%3};"
        : "+f"(d[0]), "+f"(d[1]), "+f"(d[2]), "+f"(d[3])
        : "r"(a[0]), "r"(a[1]), "r"(a[2]), "r"(a[3]), "r"(b0), "r"(b1));
}

// ---------------------------------------------------------------------------
// Fused conv: in-kernel 2-way fp16 split + HMMA implicit GEMM.
// CTA = (n, 8h x 32w): M=256 positions, N=32 co. Warp hh = one h row (32 w).
// Staging (conflict-free): lane = halo position, each lane gathers one
// 8-channel octet via 8 w-coalesced LDGs, splits to h1/h2, writes one
// STS.128 per plane at [pos*80 + oct*16] (addr16 = 5*pos+oct -> per-quarter
// distinct mod 8 -> conflict-free).
// B: binarized weights fp16, 288 k x 32 o, pitch 80B.
// Mainloop: 9 taps x 2 k16-chunks x { 2 ldsm4t(B); per plane: 2 ldsm4(A), 8 mma }.
// ---------------------------------------------------------------------------
#define A_PLANE_B 27200     // 340 * 80
#define B_OFF     54400     // 2 planes
#define CONV_SMEM 77440     // + 288*80 B

__global__ __launch_bounds__(256, 2)
void conv_kernel(const float* __restrict__ x, const float* __restrict__ wgt,
                 float* __restrict__ out)
{
    extern __shared__ unsigned char dsm[];
    __half* Bsm = (__half*)(dsm + B_OFF);
    float* smt = (float*)dsm;            // alias after mainloop: 256 m x 36 f32
    __shared__ double sred[512];

    const int tid = threadIdx.x;
    const int l = tid & 31, hh = tid >> 5;
    const int w0 = blockIdx.x * 32, h0 = blockIdx.y * 8, n = blockIdx.z;
    const uint32_t Abase = smem_u32(dsm);
    const uint32_t Bbase = smem_u32(Bsm);
    const uint32_t laneoff = (uint32_t)(((((l >> 3) & 1) * 8) + (l & 7)) * 80 + (l >> 4) * 16);

    // ---- stage B: binarized weights fp16, Bsm[k = tap*32+c][o], pitch 40 h ----
    for (int i = tid; i < 288 * 32; i += 256) {
        int k = i >> 5, o = i & 31;
        int tap = k >> 5, c = k & 31;
        Bsm[k * 40 + o] = __float2half_rn((wgt[o * 288 + c * 9 + tap] >= 0.0f) ? 1.0f : -1.0f);
    }

    // ---- stage A: 340 halo positions, lane = position, octet-gather ----
    for (int pb = hh; pb < 11; pb += 8) {
        const int pos = pb * 32 + l;
        const bool pvalid = pos < 340;
        int r = 0, pc = 0;
        if (pvalid) { r = pos / 34; pc = pos - r * 34; }
        const int gh = h0 + r - 1, gw = w0 + pc - 1;
        const bool in = pvalid && gh >= 0 && gh < HH && gw >= 0 && gw < WW;
        const float* xb = x + (size_t)n * 32 * NPIX + (size_t)gh * 224 + gw;
#pragma unroll
        for (int oct = 0; oct < 4; oct++) {
            uint32_t u1[4], u2[4];
#pragma unroll
            for (int j = 0; j < 4; j++) {
                const float va = in ? xb[(size_t)(8 * oct + 2 * j) * NPIX]     : 0.0f;
                const float vb = in ? xb[(size_t)(8 * oct + 2 * j + 1) * NPIX] : 0.0f;
                const __half a1 = __float2half_rn(va);
                const __half b1 = __float2half_rn(vb);
                const __half a2 = __float2half_rn(va - __half2float(a1));
                const __half b2 = __float2half_rn(vb - __half2float(b1));
                u1[j] = (uint32_t)__half_as_ushort(a1) | ((uint32_t)__half_as_ushort(b1) << 16);
                u2[j] = (uint32_t)__half_as_ushort(a2) | ((uint32_t)__half_as_ushort(b2) << 16);
            }
            if (pvalid) {
                *(uint4*)(dsm + pos * 80 + oct * 16) =
                    make_uint4(u1[0], u1[1], u1[2], u1[3]);
                *(uint4*)(dsm + A_PLANE_B + pos * 80 + oct * 16) =
                    make_uint4(u2[0], u2[1], u2[2], u2[3]);
            }
        }
    }
    __syncthreads();

    float acc[2][4][4];
#pragma unroll
    for (int a = 0; a < 2; a++)
#pragma unroll
        for (int b = 0; b < 4; b++)
#pragma unroll
            for (int c = 0; c < 4; c++) acc[a][b][c] = 0.0f;

#pragma unroll
    for (int tap = 0; tap < 9; tap++) {
        const int dy = tap / 3, dx = tap - (tap / 3) * 3;
#pragma unroll
        for (int ch = 0; ch < 2; ch++) {
            uint32_t Bf[8];
            uint32_t bp = Bbase + (uint32_t)((tap * 32 + ch * 16) * 80) + laneoff;
            ldsm4t(Bf,     bp);          // o 0-15 : {b0,b1 | b0,b1}
            ldsm4t(Bf + 4, bp + 32);     // o 16-31
            const uint32_t apos = (uint32_t)((((hh + dy) * 34 + dx) * 80) + ch * 32) + laneoff;
#pragma unroll
            for (int s = 0; s < 2; s++) {
                uint32_t A0[4], A1[4];
                uint32_t ap = Abase + (uint32_t)(s * A_PLANE_B) + apos;
                ldsm4(A0, ap);
                ldsm4(A1, ap + 1280);    // +16 positions (mi=1)
#pragma unroll
                for (int ni = 0; ni < 4; ni++) {
                    mma4(acc[0][ni], A0, Bf[ni * 2], Bf[ni * 2 + 1]);
                    mma4(acc[1][ni], A1, Bf[ni * 2], Bf[ni * 2 + 1]);
                }
            }
        }
    }

    // ---- epilogue: accums -> smt[m][o] (pitch 36), stats, coalesced store ----
    __syncthreads();   // done reading A/B smem; smt aliases them
    {
        const int g = l >> 2, t4 = l & 3;
#pragma unroll
        for (int mi = 0; mi < 2; mi++) {
            int m0 = hh * 32 + mi * 16 + g;
#pragma unroll
            for (int ni = 0; ni < 4; ni++) {
                int o0 = ni * 8 + 2 * t4;
                smt[m0 * 36 + o0]           = acc[mi][ni][0];
                smt[m0 * 36 + o0 + 1]       = acc[mi][ni][1];
                smt[(m0 + 8) * 36 + o0]     = acc[mi][ni][2];
                smt[(m0 + 8) * 36 + o0 + 1] = acc[mi][ni][3];
            }
        }
    }
    __syncthreads();

    // BN stats: f32 inner (32 values), double outer (fixed order -> deterministic)
    {
        const int o = tid & 31, part = tid >> 5;
        float s = 0.0f, q = 0.0f;
#pragma unroll
        for (int m = part * 32; m < part * 32 + 32; m++) {
            float v = smt[m * 36 + o];
            s += v;
            q = fmaf(v, v, q);
        }
        sred[o * 8 + part]       = (double)s;
        sred[256 + o * 8 + part] = (double)q;
    }

    // Store: thread = position m; per o, warp lanes = 32 consecutive w (coalesced)
    {
        const int hhm = tid >> 5, wwm = tid & 31;
        float* obase = out + (size_t)n * 32 * NPIX
                           + (size_t)(h0 + hhm) * 224 + w0 + wwm;
#pragma unroll
        for (int j = 0; j < 8; j++) {
            float v0 = smt[tid * 36 + j * 4 + 0];
            float v1 = smt[tid * 36 + j * 4 + 1];
            float v2 = smt[tid * 36 + j * 4 + 2];
            float v3 = smt[tid * 36 + j * 4 + 3];
            obase[(size_t)(j * 4 + 0) * NPIX] = v0;
            obase[(size_t)(j * 4 + 1) * NPIX] = v1;
            obase[(size_t)(j * 4 + 2) * NPIX] = v2;
            obase[(size_t)(j * 4 + 3) * NPIX] = v3;
        }
    }
    __syncthreads();

    const int bflat = blockIdx.x + GX * (blockIdx.y + GY * blockIdx.z);
    if (tid < 64) {
        int cch = tid & 31, which = tid >> 5;
        double a = 0.0;
#pragma unroll
        for (int j = 0; j < 8; j++)
            a += sred[which * 256 + cch * 8 + j];
        g_part[bflat * 64 + which * 32 + cch] = a;
    }
}

// ---------------------------------------------------------------------------
__global__ void reduce_kernel(const float* __restrict__ gamma,
                              const float* __restrict__ beta)
{
    const int c = blockIdx.x, t = threadIdx.x;   // 32 blocks x 256 threads
    __shared__ double sh[512];
    double s = 0.0, q = 0.0;
    for (int b = t; b < NBLK; b += 256) {
        s += g_part[b * 64 + c];
        q += g_part[b * 64 + 32 + c];
    }
    sh[t] = s; sh[256 + t] = q;
    __syncthreads();
    for (int step = 128; step > 0; step >>= 1) {
        if (t < step) { sh[t] += sh[t + step]; sh[256 + t] += sh[256 + t + step]; }
        __syncthreads();
    }
    if (t == 0) {
        const double Nc = (double)NB * HH * WW;
        double mean = sh[0] / Nc;
        double var  = sh[256] / Nc - mean * mean;
        double inv  = 1.0 / sqrt(var + 1e-5);
        double sc   = (double)gamma[c] * inv;
        g_scale[c] = (float)sc;
        g_bias[c]  = (float)((double)beta[c] - mean * sc);
    }
}

// ---------------------------------------------------------------------------
__device__ __forceinline__ float qclamp(float v, float sc, float bi)
{
    float y = fmaf(v, sc, bi);
    y = fminf(fmaxf(y, -1.0f), 1.0f);
    return rintf(y * 2.0f) * 0.5f;
}

__global__ void finalize_kernel(float4* __restrict__ out)
{
    const unsigned i = blockIdx.x * 256u + threadIdx.x;   // < 6422528
    const int c = (int)((i / 12544u) & 31u);
    const float sc = g_scale[c], bi = g_bias[c];
    float4 v = out[i];
    v.x = qclamp(v.x, sc, bi); v.y = qclamp(v.y, sc, bi);
    v.z = qclamp(v.z, sc, bi); v.w = qclamp(v.w, sc, bi);
    out[i] = v;
}

// ---------------------------------------------------------------------------
extern "C" void kernel_launch(void* const* d_in, const int* in_sizes, int n_in,
                              void* d_out, int out_size)
{
    const float* x     = (const float*)d_in[0];
    const float* wgt   = (const float*)d_in[1];
    const float* gamma = (const float*)d_in[2];
    const float* beta  = (const float*)d_in[3];
    float* out = (float*)d_out;

    cudaFuncSetAttribute(conv_kernel, cudaFuncAttributeMaxDynamicSharedMemorySize, CONV_SMEM);

    conv_kernel<<<dim3(GX, GY, NB), 256, CONV_SMEM>>>(x, wgt, out);
    reduce_kernel<<<32, 256>>>(gamma, beta);
    finalize_kernel<<<25088, 256>>>((float4*)d_out);
}